// round 1
// baseline (speedup 1.0000x reference)
#include <cuda_runtime.h>
#include <cstddef>

#define TB 64
#define TT 1024
#define TI 64
#define TH 512
#define TR 8
#define TO 64

// Scratch for the precomputed input drive, laid out [T, B, H].
__device__ float g_inp[(size_t)TT * TB * TH];

__device__ __forceinline__ float fast_tanh(float x) {
    float y;
    asm("tanh.approx.f32 %0, %1;" : "=f"(y) : "f"(x));
    return y;
}

// ---------------------------------------------------------------------------
// Kernel 1: g_inp[(t*B + b)*H + h] = b_in[h] + sum_i u[b,t,i] * W_in[h,i]
// Grid: (TT, TH/64), block 256. Tile: 64 rows (all b for one t) x 64 h, K=64.
// ---------------------------------------------------------------------------
__global__ void __launch_bounds__(256) k_inp(const float* __restrict__ u,
                                             const float* __restrict__ W_in,
                                             const float* __restrict__ b_in)
{
    __shared__ float as[64 * 64];  // as[k*64 + (b ^ sw(k))]
    __shared__ float bs[64 * 64];  // bs[k*64 + (h ^ sw(k))]
    const int t   = blockIdx.x;        // 0..1023
    const int bn  = blockIdx.y;        // 0..7  (h block)
    const int tid = threadIdx.x;

#pragma unroll
    for (int s = 0; s < 16; s++) {
        int i = tid + s * 256;
        int r = i >> 6;        // row within tile (b for A, h-offset for B)
        int k = i & 63;
        int sw = (k & 15) << 2;
        as[k * 64 + (r ^ sw)] = u[((size_t)((r << 10) + t)) * 64 + k];
        bs[k * 64 + (r ^ sw)] = W_in[(size_t)(bn * 64 + r) * 64 + k];
    }
    __syncthreads();

    const int tx = tid & 15;   // h sub-block (4 cols)
    const int ty = tid >> 4;   // b sub-block (4 rows)
    float acc[4][4];
#pragma unroll
    for (int i = 0; i < 4; i++)
#pragma unroll
        for (int j = 0; j < 4; j++) acc[i][j] = 0.f;

#pragma unroll
    for (int k = 0; k < 64; k++) {
        int sw = (k & 15) << 2;
        float4 a = *(const float4*)&as[k * 64 + ((ty * 4) ^ sw)];
        float4 w = *(const float4*)&bs[k * 64 + ((tx * 4) ^ sw)];
        float av[4] = {a.x, a.y, a.z, a.w};
        float wv[4] = {w.x, w.y, w.z, w.w};
#pragma unroll
        for (int i = 0; i < 4; i++)
#pragma unroll
            for (int j = 0; j < 4; j++)
                acc[i][j] = fmaf(av[i], wv[j], acc[i][j]);
    }

    const int h0 = bn * 64 + tx * 4;
    float4 bias = *(const float4*)&b_in[h0];
    float bv[4] = {bias.x, bias.y, bias.z, bias.w};
#pragma unroll
    for (int i = 0; i < 4; i++) {
        int m = (t << 6) + ty * 4 + i;   // m = t*64 + b
        float4 o;
        o.x = acc[i][0] + bv[0];
        o.y = acc[i][1] + bv[1];
        o.z = acc[i][2] + bv[2];
        o.w = acc[i][3] + bv[3];
        *(float4*)&g_inp[(size_t)m * TH + h0] = o;
    }
}

// ---------------------------------------------------------------------------
// Kernel 2: the sequential scan. One block per batch b, 512 threads (one per h).
// Per step: r = tanh(x); a_j = r@M, b_j = r@N (16 warp-owned dot products);
// rec[h] = scale * sum_j (a_j*b_j) * L[h,j];
// x <- x + 0.05*noise + 0.2*(-x + rec + inp). traj[b,t,h] = x.
// ---------------------------------------------------------------------------
__global__ void __launch_bounds__(512, 1) k_scan(const float* __restrict__ noise,
                                                 const float* __restrict__ x0,
                                                 const float* __restrict__ L,
                                                 const float* __restrict__ Mw,
                                                 const float* __restrict__ Nw,
                                                 float* __restrict__ traj,
                                                 float* __restrict__ xlast)
{
    __shared__ float r_s[TH];
    __shared__ float sums[16];

    const int b    = blockIdx.x;
    const int h    = threadIdx.x;
    const int wid  = h >> 5;     // 0..15 : which dot-product this warp owns
    const int lane = h & 31;

    // L row for this h (rank-8 expansion coefficients)
    float Lr[TR];
#pragma unroll
    for (int j = 0; j < TR; j++) Lr[j] = L[h * TR + j];

    // Coefficients for this warp's dot product, strided over h = lane + 32*s.
    // wid < 8 -> column wid of M ; wid >= 8 -> column wid-8 of N.
    const float* C = (wid < 8) ? Mw : Nw;
    const int jj = wid & 7;
    float coefR[16];
#pragma unroll
    for (int s = 0; s < 16; s++) coefR[s] = C[(lane + 32 * s) * TR + jj];

    float x = x0[b * TH + h];
    const float scale = 1.0f / ((float)TH * (float)TH);

    // 2-deep prefetch of inp and noise (both [T,B,H])
    size_t base0 = (size_t)b * TH + h;                    // t = 0
    size_t base1 = ((size_t)TB * TH) + base0;             // t = 1
    float inp_a = g_inp[base0], noi_a = noise[base0];
    float inp_b = g_inp[base1], noi_b = noise[base1];

    float* trajp = traj + ((size_t)b * TT) * TH + h;

    for (int t = 0; t < TT; t++) {
        float r = fast_tanh(x);
        r_s[h] = r;
        __syncthreads();

        // Stage 1: warp 'wid' computes sum_h r[h] * coef[h]
        float acc = 0.f;
#pragma unroll
        for (int s = 0; s < 16; s++)
            acc = fmaf(r_s[lane + 32 * s], coefR[s], acc);
#pragma unroll
        for (int off = 16; off; off >>= 1)
            acc += __shfl_xor_sync(0xffffffffu, acc, off);
        if (lane == 0) sums[wid] = acc;
        __syncthreads();

        // Stage 2: every thread expands the rank-8 term for its h.
        float rec = 0.f;
#pragma unroll
        for (int j = 0; j < TR; j++)
            rec = fmaf(sums[j] * sums[j + TR], Lr[j], rec);

        float xn = x + 0.05f * noi_a + 0.2f * (fmaf(rec, scale, inp_a) - x);
        trajp[(size_t)t * TH] = xn;
        x = xn;

        // rotate prefetch registers and issue next loads (t+2)
        inp_a = inp_b; noi_a = noi_b;
        if (t + 2 < TT) {
            size_t off2 = ((size_t)(t + 2) * TB + b) * TH + h;
            inp_b = g_inp[off2];
            noi_b = noise[off2];
        }
    }
    xlast[b * TH + h] = x;
}

// ---------------------------------------------------------------------------
// Kernel 3: out[m, o] = b_out[o] + sum_h tanh(traj[m, h]) * W_out[o, h]
// m = b*T + t (65536 rows). Grid: 1024 blocks, 256 threads.
// Tile: 64 rows x 64 cols (all O), K in 8 chunks of 64.
// ---------------------------------------------------------------------------
__global__ void __launch_bounds__(256) k_out(const float* __restrict__ traj,
                                             const float* __restrict__ W_out,
                                             const float* __restrict__ b_out,
                                             float* __restrict__ outp)
{
    __shared__ float at[64 * 64];   // at[k*64 + (row ^ sw)]
    __shared__ float bs2[64 * 64];  // bs2[k*64 + (o ^ sw)]
    const int bm  = blockIdx.x;     // row block
    const int tid = threadIdx.x;
    const int tx = tid & 15;        // o sub-block
    const int ty = tid >> 4;        // row sub-block

    float acc[4][4];
#pragma unroll
    for (int i = 0; i < 4; i++)
#pragma unroll
        for (int j = 0; j < 4; j++) acc[i][j] = 0.f;

    for (int kc = 0; kc < 8; kc++) {
        __syncthreads();
#pragma unroll
        for (int s = 0; s < 16; s++) {
            int i = tid + s * 256;
            int r = i >> 6;
            int k = i & 63;
            int sw = (k & 15) << 2;
            float tv = traj[((size_t)(bm * 64 + r)) * TH + kc * 64 + k];
            at[k * 64 + (r ^ sw)]  = tanhf(tv);
            bs2[k * 64 + (r ^ sw)] = W_out[(size_t)r * TH + kc * 64 + k];
        }
        __syncthreads();
#pragma unroll
        for (int k = 0; k < 64; k++) {
            int sw = (k & 15) << 2;
            float4 a = *(const float4*)&at[k * 64 + ((ty * 4) ^ sw)];
            float4 w = *(const float4*)&bs2[k * 64 + ((tx * 4) ^ sw)];
            float av[4] = {a.x, a.y, a.z, a.w};
            float wv[4] = {w.x, w.y, w.z, w.w};
#pragma unroll
            for (int i = 0; i < 4; i++)
#pragma unroll
                for (int j = 0; j < 4; j++)
                    acc[i][j] = fmaf(av[i], wv[j], acc[i][j]);
        }
    }

    const int o0 = tx * 4;
    float4 bias = *(const float4*)&b_out[o0];
    float bv[4] = {bias.x, bias.y, bias.z, bias.w};
#pragma unroll
    for (int i = 0; i < 4; i++) {
        int m = bm * 64 + ty * 4 + i;
        float4 o;
        o.x = acc[i][0] + bv[0];
        o.y = acc[i][1] + bv[1];
        o.z = acc[i][2] + bv[2];
        o.w = acc[i][3] + bv[3];
        *(float4*)&outp[(size_t)m * TO + o0] = o;
    }
}

// ---------------------------------------------------------------------------
// Launcher. Inputs (metadata order): u, x0, noise, L, M, N, W_in, b_in,
// W_out, b_out. Output buffer: [output | x_last | traj] concatenated.
// ---------------------------------------------------------------------------
extern "C" void kernel_launch(void* const* d_in, const int* in_sizes, int n_in,
                              void* d_out, int out_size)
{
    (void)in_sizes; (void)n_in; (void)out_size;
    const float* u     = (const float*)d_in[0];
    const float* x0    = (const float*)d_in[1];
    const float* noise = (const float*)d_in[2];
    const float* L     = (const float*)d_in[3];
    const float* Mw    = (const float*)d_in[4];
    const float* Nw    = (const float*)d_in[5];
    const float* W_in  = (const float*)d_in[6];
    const float* b_in  = (const float*)d_in[7];
    const float* W_out = (const float*)d_in[8];
    const float* b_out = (const float*)d_in[9];

    float* outp  = (float*)d_out;
    float* xlast = outp + (size_t)TB * TT * TO;
    float* traj  = xlast + (size_t)TB * TH;

    dim3 g1(TT, TH / 64);
    k_inp<<<g1, 256>>>(u, W_in, b_in);
    k_scan<<<TB, 512>>>(noise, x0, L, Mw, Nw, traj, xlast);
    k_out<<<(TB * TT) / 64, 256>>>(traj, W_out, b_out, outp);
}